// round 3
// baseline (speedup 1.0000x reference)
#include <cuda_runtime.h>

typedef unsigned long long ull;

#define TT       30
#define BB       1048576
#define THREADS  256
#define HALF     (BB / 2)
#define CH       10          // timesteps per staged phase
#define NPH      (TT / CH)   // 3 phases
#define REG_FLOATS (THREADS * CH)   // 2560 floats per region per phase

// Weights in constant memory (uniform-indexed).
__constant__ __align__(16) float cW1[TT * 2 * 20];  // 1200 floats
__constant__ __align__(16) float cB1[TT * 20];      // 600
__constant__ __align__(16) float cW2[TT * 20];      // 600
__constant__ __align__(16) float cB2[TT];           // 30

// ---------------- packed f32x2 helpers ----------------
__device__ __forceinline__ ull pk(float lo, float hi) {
    ull r; asm("mov.b64 %0, {%1,%2};" : "=l"(r) : "f"(lo), "f"(hi)); return r;
}
__device__ __forceinline__ void upk(float& lo, float& hi, ull v) {
    asm("mov.b64 {%0,%1}, %2;" : "=f"(lo), "=f"(hi) : "l"(v));
}
__device__ __forceinline__ ull fma2(ull a, ull b, ull c) {
    ull d; asm("fma.rn.f32x2 %0, %1, %2, %3;" : "=l"(d) : "l"(a), "l"(b), "l"(c)); return d;
}
__device__ __forceinline__ ull add2(ull a, ull b) {
    ull d; asm("add.rn.f32x2 %0, %1, %2;" : "=l"(d) : "l"(a), "l"(b)); return d;
}
__device__ __forceinline__ ull relu2(ull v) {
    float a, b; upk(a, b, v);
    return pk(fmaxf(a, 0.0f), fmaxf(b, 0.0f));
}
// tanh(z) = 1 - 2/(exp(2z)+1) via MUFU.EX2 + MUFU.RCP (~1e-6 rel err)
__device__ __forceinline__ float fast_tanh(float z) {
    float e; asm("ex2.approx.f32 %0, %1;" : "=f"(e) : "f"(z * 2.8853900817779268f));
    float r; asm("rcp.approx.f32 %0, %1;" : "=f"(r) : "f"(e + 1.0f));
    return fmaf(-2.0f, r, 1.0f);
}

// Shared: 2 regions x 256 elems x CH floats = 5120 floats = 20480 bytes
#define SMEM_FLOATS (2 * REG_FLOATS)

__global__ __launch_bounds__(THREADS, 6)
void rnn_kernel(const float* __restrict__ gx,
                float* __restrict__ gout)
{
    __shared__ float sIO[SMEM_FLOATS];

    const int tid = threadIdx.x;
    const int base0 = blockIdx.x * THREADS;        // region 0 element base
    const int base1 = base0 + HALF;                // region 1 element base

    // ---- stage x for phase 0 ----
    #pragma unroll 1
    for (int i = tid; i < REG_FLOATS; i += THREADS) {
        unsigned e = (unsigned)i / CH;
        unsigned j = (unsigned)i - e * CH;
        sIO[i]              = gx[(size_t)(base0 + e) * TT + j];
        sIO[REG_FLOATS + i] = gx[(size_t)(base1 + e) * TT + j];
    }
    __syncthreads();

    float* io0 = sIO + tid * CH;
    float* io1 = sIO + REG_FLOATS + tid * CH;

    const ull* w1u = (const ull*)cW1;   // per t: 20 ulls (10 row0 pairs, 10 row1 pairs)
    const ull* b1u = (const ull*)cB1;   // per t: 10 ulls
    const ull* w2u = (const ull*)cW2;   // per t: 10 ulls

    float o0 = 0.0f, o1 = 0.0f;

    #pragma unroll 1
    for (int p = 0; p < NPH; ++p) {
        // ---- compute CH timesteps ----
        #pragma unroll 1
        for (int jj = 0; jj < CH; ++jj) {
            const int t = p * CH + jj;
            const ulonglong2* w1t = (const ulonglong2*)(w1u + t * 20);
            const ulonglong2* b1t = (const ulonglong2*)(b1u + t * 10);
            const ulonglong2* w2t = (const ulonglong2*)(w2u + t * 10);
            const float bt2 = cB2[t];
            const float x0  = io0[jj];
            const float x1  = io1[jj];

            ull xx0 = pk(x0, x0), oo0 = pk(o0, o0);
            ull xx1 = pk(x1, x1), oo1 = pk(o1, o1);
            ull accA0 = pk(bt2, 0.0f), accB0 = pk(0.0f, 0.0f);
            ull accA1 = accA0,         accB1 = accB0;

            #pragma unroll
            for (int q = 0; q < 5; ++q) {
                ulonglong2 wa = w1t[q];       // W1 row0, hidden 4q..4q+3
                ulonglong2 wb = w1t[5 + q];   // W1 row1
                ulonglong2 bb = b1t[q];       // b1
                ulonglong2 w2 = w2t[q];       // W2

                ull hA0 = fma2(xx0, wa.x, fma2(oo0, wb.x, bb.x));
                ull hB0 = fma2(xx0, wa.y, fma2(oo0, wb.y, bb.y));
                ull hA1 = fma2(xx1, wa.x, fma2(oo1, wb.x, bb.x));
                ull hB1 = fma2(xx1, wa.y, fma2(oo1, wb.y, bb.y));

                accA0 = fma2(relu2(hA0), w2.x, accA0);
                accB0 = fma2(relu2(hB0), w2.y, accB0);
                accA1 = fma2(relu2(hA1), w2.x, accA1);
                accB1 = fma2(relu2(hB1), w2.y, accB1);
            }
            {
                float a, b;
                upk(a, b, add2(accA0, accB0));
                o0 = fast_tanh(a + b);
                upk(a, b, add2(accA1, accB1));
                o1 = fast_tanh(a + b);
            }
            io0[jj] = o0;   // overwrite consumed x slot with output
            io1[jj] = o1;
        }
        __syncthreads();

        // ---- writeback this phase's outputs; restage next phase's x ----
        // Same thread handles the same smem slot for both -> no intra-loop hazard.
        const int last = (p == NPH - 1);
        #pragma unroll 1
        for (int i = tid; i < REG_FLOATS; i += THREADS) {
            unsigned e = (unsigned)i / CH;
            unsigned j = (unsigned)i - e * CH;
            size_t g0 = (size_t)(base0 + e) * TT + p * CH + j;
            size_t g1 = (size_t)(base1 + e) * TT + p * CH + j;
            gout[g0] = sIO[i];
            gout[g1] = sIO[REG_FLOATS + i];
            if (!last) {
                sIO[i]              = gx[g0 + CH];
                sIO[REG_FLOATS + i] = gx[g1 + CH];
            }
        }
        __syncthreads();
    }
}

extern "C" void kernel_launch(void* const* d_in, const int* in_sizes, int n_in,
                              void* d_out, int out_size)
{
    const float* x = (const float*)d_in[0];

    // Populate constant bank (graph-capturable D2D memcpys, no allocation).
    void *pW1, *pB1, *pW2, *pB2;
    cudaGetSymbolAddress(&pW1, cW1);
    cudaGetSymbolAddress(&pB1, cB1);
    cudaGetSymbolAddress(&pW2, cW2);
    cudaGetSymbolAddress(&pB2, cB2);
    cudaMemcpyAsync(pW1, d_in[1], sizeof(float) * TT * 2 * 20, cudaMemcpyDeviceToDevice);
    cudaMemcpyAsync(pB1, d_in[2], sizeof(float) * TT * 20,     cudaMemcpyDeviceToDevice);
    cudaMemcpyAsync(pW2, d_in[3], sizeof(float) * TT * 20,     cudaMemcpyDeviceToDevice);
    cudaMemcpyAsync(pB2, d_in[4], sizeof(float) * TT,          cudaMemcpyDeviceToDevice);

    rnn_kernel<<<BB / (2 * THREADS), THREADS>>>(x, (float*)d_out);
}

// round 4
// speedup vs baseline: 1.9672x; 1.9672x over previous
#include <cuda_runtime.h>

typedef unsigned long long ull;

#define TT       30
#define BB       1048576
#define THREADS  256
#define HALF     (BB / 2)

// Small weights stay in constant memory (LDC port); W1 goes to shared (LDS port).
__constant__ __align__(16) float cB1[TT * 20];      // 600 floats
__constant__ __align__(16) float cW2[TT * 20];      // 600
__constant__ __align__(16) float cB2[TT];           // 30

// ---------------- packed f32x2 helpers ----------------
__device__ __forceinline__ ull pk(float lo, float hi) {
    ull r; asm("mov.b64 %0, {%1,%2};" : "=l"(r) : "f"(lo), "f"(hi)); return r;
}
__device__ __forceinline__ void upk(float& lo, float& hi, ull v) {
    asm("mov.b64 {%0,%1}, %2;" : "=f"(lo), "=f"(hi) : "l"(v));
}
__device__ __forceinline__ ull fma2(ull a, ull b, ull c) {
    ull d; asm("fma.rn.f32x2 %0, %1, %2, %3;" : "=l"(d) : "l"(a), "l"(b), "l"(c)); return d;
}
__device__ __forceinline__ ull add2(ull a, ull b) {
    ull d; asm("add.rn.f32x2 %0, %1, %2;" : "=l"(d) : "l"(a), "l"(b)); return d;
}
__device__ __forceinline__ ull relu2(ull v) {
    float a, b; upk(a, b, v);
    return pk(fmaxf(a, 0.0f), fmaxf(b, 0.0f));
}
// tanh(z) = 1 - 2/(exp(2z)+1) via MUFU.EX2 + MUFU.RCP (~1e-6 rel err)
__device__ __forceinline__ float fast_tanh(float z) {
    float e; asm("ex2.approx.f32 %0, %1;" : "=f"(e) : "f"(z * 2.8853900817779268f));
    float r; asm("rcp.approx.f32 %0, %1;" : "=f"(r) : "f"(e + 1.0f));
    return fmaf(-2.0f, r, 1.0f);
}

// Shared layout (floats):
//   sW1 : [0, 1200)       W1 [T][2][20]
//   sIO : [1200, 16560)   x/out staging: 2 regions x 256 elems x 30 floats
#define SMEM_FLOATS (1200 + 2 * THREADS * TT)   // 16560 floats = 66240 bytes

__global__ __launch_bounds__(THREADS, 3)
void rnn_kernel(const float* __restrict__ gx,
                const float* __restrict__ gW1,
                float* __restrict__ gout)
{
    extern __shared__ float smem[];
    float* sW1 = smem;
    float* sIO = smem + 1200;

    const int tid = threadIdx.x;
    const int base0 = blockIdx.x * THREADS;  // element base, region 0

    // ---- stage W1 (coalesced float4) ----
    {
        float4*       d = (float4*)sW1;
        const float4* s = (const float4*)gW1;
        for (int i = tid; i < 300; i += THREADS) d[i] = s[i];
    }
    // ---- stage x (coalesced float4: per-region 256*30 floats = 1920 float4) ----
    {
        float4*       d  = (float4*)sIO;
        const float4* s0 = (const float4*)(gx + (size_t)base0 * TT);
        const float4* s1 = (const float4*)(gx + (size_t)(base0 + HALF) * TT);
        for (int i = tid; i < 1920; i += THREADS) d[i]        = s0[i];
        for (int i = tid; i < 1920; i += THREADS) d[1920 + i] = s1[i];
    }
    __syncthreads();

    float* io0 = sIO + tid * TT;                // this thread's element (region 0)
    float* io1 = sIO + (THREADS + tid) * TT;    // this thread's element (region 1)

    const ull* w1u = (const ull*)sW1;   // per t: 20 ulls (10 row0 pairs, 10 row1 pairs)
    const ull* b1u = (const ull*)cB1;   // per t: 10 ulls
    const ull* w2u = (const ull*)cW2;   // per t: 10 ulls

    float o0 = 0.0f, o1 = 0.0f;

    #pragma unroll 1
    for (int t = 0; t < TT; ++t) {
        const ulonglong2* w1t = (const ulonglong2*)(w1u + t * 20);  // shared (LDS)
        const ulonglong2* b1t = (const ulonglong2*)(b1u + t * 10);  // constant (LDC)
        const ulonglong2* w2t = (const ulonglong2*)(w2u + t * 10);  // constant (LDC)
        const float bt2 = cB2[t];
        const float x0  = io0[t];
        const float x1  = io1[t];

        ull xx0 = pk(x0, x0), oo0 = pk(o0, o0);
        ull xx1 = pk(x1, x1), oo1 = pk(o1, o1);
        ull accA0 = pk(bt2, 0.0f), accB0 = pk(0.0f, 0.0f);
        ull accA1 = accA0,         accB1 = accB0;

        #pragma unroll
        for (int q = 0; q < 5; ++q) {
            ulonglong2 wa = w1t[q];       // W1 row0, hidden 4q..4q+3  (LDS.128)
            ulonglong2 wb = w1t[5 + q];   // W1 row1                    (LDS.128)
            ulonglong2 bb = b1t[q];       // b1                         (LDC.128)
            ulonglong2 w2 = w2t[q];       // W2                         (LDC.128)

            ull hA0 = fma2(xx0, wa.x, fma2(oo0, wb.x, bb.x));
            ull hB0 = fma2(xx0, wa.y, fma2(oo0, wb.y, bb.y));
            ull hA1 = fma2(xx1, wa.x, fma2(oo1, wb.x, bb.x));
            ull hB1 = fma2(xx1, wa.y, fma2(oo1, wb.y, bb.y));

            accA0 = fma2(relu2(hA0), w2.x, accA0);
            accB0 = fma2(relu2(hB0), w2.y, accB0);
            accA1 = fma2(relu2(hA1), w2.x, accA1);
            accB1 = fma2(relu2(hB1), w2.y, accB1);
        }
        {
            float a, b;
            upk(a, b, add2(accA0, accB0));
            o0 = fast_tanh(a + b);
            upk(a, b, add2(accA1, accB1));
            o1 = fast_tanh(a + b);
        }
        io0[t] = o0;    // overwrite consumed x slot with output
        io1[t] = o1;
    }

    __syncthreads();

    // ---- writeback (coalesced float4) ----
    {
        const float4* s  = (const float4*)sIO;
        float4*       d0 = (float4*)(gout + (size_t)base0 * TT);
        float4*       d1 = (float4*)(gout + (size_t)(base0 + HALF) * TT);
        for (int i = tid; i < 1920; i += THREADS) d0[i] = s[i];
        for (int i = tid; i < 1920; i += THREADS) d1[i] = s[1920 + i];
    }
}

extern "C" void kernel_launch(void* const* d_in, const int* in_sizes, int n_in,
                              void* d_out, int out_size)
{
    const float* x  = (const float*)d_in[0];
    const float* W1 = (const float*)d_in[1];

    // Populate constant bank (graph-capturable D2D memcpys, no allocation).
    void *pB1, *pW2, *pB2;
    cudaGetSymbolAddress(&pB1, cB1);
    cudaGetSymbolAddress(&pW2, cW2);
    cudaGetSymbolAddress(&pB2, cB2);
    cudaMemcpyAsync(pB1, d_in[2], sizeof(float) * TT * 20, cudaMemcpyDeviceToDevice);
    cudaMemcpyAsync(pW2, d_in[3], sizeof(float) * TT * 20, cudaMemcpyDeviceToDevice);
    cudaMemcpyAsync(pB2, d_in[4], sizeof(float) * TT,      cudaMemcpyDeviceToDevice);

    const int smem_bytes = SMEM_FLOATS * (int)sizeof(float);  // 66240
    cudaFuncSetAttribute(rnn_kernel, cudaFuncAttributeMaxDynamicSharedMemorySize, smem_bytes);

    rnn_kernel<<<BB / (2 * THREADS), THREADS, smem_bytes>>>(x, W1, (float*)d_out);
}

// round 6
// speedup vs baseline: 2.0221x; 1.0279x over previous
#include <cuda_runtime.h>

typedef unsigned long long ull;

#define TT       30
#define BB       1048576
#define THREADS  128
#define M        4
#define QUARTER  (BB / 4)

// Small weights in constant (LDC port); W1 in shared (LDS port).
__constant__ __align__(16) float cB1[TT * 20];      // 600 floats
__constant__ __align__(16) float cW2[TT * 20];      // 600
__constant__ __align__(16) float cB2[TT];           // 30

// ---------------- packed f32x2 helpers ----------------
__device__ __forceinline__ ull pk(float lo, float hi) {
    ull r; asm("mov.b64 %0, {%1,%2};" : "=l"(r) : "f"(lo), "f"(hi)); return r;
}
__device__ __forceinline__ void upk(float& lo, float& hi, ull v) {
    asm("mov.b64 {%0,%1}, %2;" : "=f"(lo), "=f"(hi) : "l"(v));
}
__device__ __forceinline__ ull fma2(ull a, ull b, ull c) {
    ull d; asm("fma.rn.f32x2 %0, %1, %2, %3;" : "=l"(d) : "l"(a), "l"(b), "l"(c)); return d;
}
__device__ __forceinline__ ull add2(ull a, ull b) {
    ull d; asm("add.rn.f32x2 %0, %1, %2;" : "=l"(d) : "l"(a), "l"(b)); return d;
}
__device__ __forceinline__ ull relu2(ull v) {
    float a, b; upk(a, b, v);
    return pk(fmaxf(a, 0.0f), fmaxf(b, 0.0f));
}
// tanh(z) = 1 - 2/(exp(2z)+1) via MUFU.EX2 + MUFU.RCP (~1e-6 rel err)
__device__ __forceinline__ float fast_tanh(float z) {
    float e; asm("ex2.approx.f32 %0, %1;" : "=f"(e) : "f"(z * 2.8853900817779268f));
    float r; asm("rcp.approx.f32 %0, %1;" : "=f"(r) : "f"(e + 1.0f));
    return fmaf(-2.0f, r, 1.0f);
}

// Shared layout (floats):
//   sW1 : [0, 1200)       W1 [T][2][20]
//   sIO : [1200, 16560)   x/out staging: M regions x 128 elems x 30 floats
#define REGF        (THREADS * TT)              // 3840 floats per region
#define SMEM_FLOATS (1200 + M * REGF)           // 16560 floats = 66240 bytes

__global__ __launch_bounds__(THREADS, 3)
void rnn_kernel(const float* __restrict__ gx,
                const float* __restrict__ gW1,
                float* __restrict__ gout)
{
    extern __shared__ float smem[];
    float* sW1 = smem;
    float* sIO = smem + 1200;

    const int tid = threadIdx.x;
    const int ebase = blockIdx.x * THREADS;   // region-0 element base

    // ---- stage W1 (coalesced float4) ----
    {
        float4*       d = (float4*)sW1;
        const float4* s = (const float4*)gW1;
        for (int i = tid; i < 300; i += THREADS) d[i] = s[i];
    }
    // ---- stage x: M regions, each 960 float4, coalesced ----
    {
        float4* d = (float4*)sIO;
        #pragma unroll
        for (int r = 0; r < M; ++r) {
            const float4* s = (const float4*)(gx + (size_t)(ebase + r * QUARTER) * TT);
            for (int i = tid; i < REGF / 4; i += THREADS) d[r * (REGF / 4) + i] = s[i];
        }
    }
    __syncthreads();

    // This thread's 4 elements
    float* io[M];
    #pragma unroll
    for (int r = 0; r < M; ++r) io[r] = sIO + r * REGF + tid * TT;

    const ull* w1u = (const ull*)sW1;   // per t: 20 ulls (10 row0 pairs, 10 row1 pairs)
    const ull* b1u = (const ull*)cB1;   // per t: 10 ulls
    const ull* w2u = (const ull*)cW2;   // per t: 10 ulls

    float o[M];
    #pragma unroll
    for (int m = 0; m < M; ++m) o[m] = 0.0f;

    #pragma unroll 2
    for (int t = 0; t < TT; ++t) {
        const ulonglong2* w1t = (const ulonglong2*)(w1u + t * 20);  // shared (LDS.128)
        const ulonglong2* b1t = (const ulonglong2*)(b1u + t * 10);  // constant (LDC.128)
        const ulonglong2* w2t = (const ulonglong2*)(w2u + t * 10);  // constant (LDC.128)
        const float bt2 = cB2[t];

        ull xx[M], oo[M], accA[M], accB[M];
        #pragma unroll
        for (int m = 0; m < M; ++m) {
            float x = io[m][t];
            xx[m]   = pk(x, x);
            oo[m]   = pk(o[m], o[m]);
            accA[m] = pk(bt2, 0.0f);
            accB[m] = pk(0.0f, 0.0f);
        }

        #pragma unroll
        for (int q = 0; q < 5; ++q) {
            ulonglong2 wa = w1t[q];       // W1 row0, hidden 4q..4q+3
            ulonglong2 wb = w1t[5 + q];   // W1 row1
            ulonglong2 bb = b1t[q];       // b1
            ulonglong2 w2 = w2t[q];       // W2

            #pragma unroll
            for (int m = 0; m < M; ++m) {
                ull hA = fma2(xx[m], wa.x, fma2(oo[m], wb.x, bb.x));
                ull hB = fma2(xx[m], wa.y, fma2(oo[m], wb.y, bb.y));
                accA[m] = fma2(relu2(hA), w2.x, accA[m]);
                accB[m] = fma2(relu2(hB), w2.y, accB[m]);
            }
        }

        #pragma unroll
        for (int m = 0; m < M; ++m) {
            float a, b;
            upk(a, b, add2(accA[m], accB[m]));
            o[m] = fast_tanh(a + b);
            io[m][t] = o[m];            // overwrite consumed x slot with output
        }
    }

    __syncthreads();

    // ---- writeback (coalesced float4) ----
    {
        const float4* s = (const float4*)sIO;
        #pragma unroll
        for (int r = 0; r < M; ++r) {
            float4* d = (float4*)(gout + (size_t)(ebase + r * QUARTER) * TT);
            for (int i = tid; i < REGF / 4; i += THREADS) d[i] = s[r * (REGF / 4) + i];
        }
    }
}

extern "C" void kernel_launch(void* const* d_in, const int* in_sizes, int n_in,
                              void* d_out, int out_size)
{
    const float* x  = (const float*)d_in[0];
    const float* W1 = (const float*)d_in[1];

    // Populate constant bank (graph-capturable D2D memcpys, no allocation).
    void *pB1, *pW2, *pB2;
    cudaGetSymbolAddress(&pB1, cB1);
    cudaGetSymbolAddress(&pW2, cW2);
    cudaGetSymbolAddress(&pB2, cB2);
    cudaMemcpyAsync(pB1, d_in[2], sizeof(float) * TT * 20, cudaMemcpyDeviceToDevice);
    cudaMemcpyAsync(pW2, d_in[3], sizeof(float) * TT * 20, cudaMemcpyDeviceToDevice);
    cudaMemcpyAsync(pB2, d_in[4], sizeof(float) * TT,      cudaMemcpyDeviceToDevice);

    const int smem_bytes = SMEM_FLOATS * (int)sizeof(float);  // 66240
    cudaFuncSetAttribute(rnn_kernel, cudaFuncAttributeMaxDynamicSharedMemorySize, smem_bytes);

    rnn_kernel<<<BB / (M * THREADS), THREADS, smem_bytes>>>(x, W1, (float*)d_out);
}